// round 1
// baseline (speedup 1.0000x reference)
#include <cuda_runtime.h>
#include <math.h>
#include <stdint.h>

#define BB 2
#define TT 2048
#define CC 2048
#define NH 16
#define NKV 4
#define HD 128
#define GC 32
#define BT (BB*TT)

// ---------------- scratch (device globals; no allocation allowed) -----------
__device__ float g_q[(size_t)BB*NH*TT*HD];   // [B,NH,T,HD]
__device__ float g_k[(size_t)BB*NKV*TT*HD];  // [B,NKV,T,HD]
__device__ float g_v[(size_t)BB*NKV*TT*HD];  // [B,NKV,T,HD]
__device__ float g_y[(size_t)BT*CC];         // [B,T,NH,HD] == [BT, C]

// ---------------- fused QKV GEMM -------------------------------------------
// out columns: [0,2048) -> Wq, [2048,2560) -> Wk, [2560,3072) -> Wv
__global__ __launch_bounds__(256) void qkv_gemm(
    const float* __restrict__ x,
    const float* __restrict__ Wq,
    const float* __restrict__ Wk,
    const float* __restrict__ Wv)
{
    __shared__ float As[16][128];
    __shared__ float Bs[16][128];

    const int bm = blockIdx.x;          // 0..31
    const int n0 = blockIdx.y * 128;    // 0..2944
    const float* W; int ldw; int wcol0; int region;
    if (n0 < 2048)      { W = Wq; ldw = 2048; wcol0 = n0;        region = 0; }
    else if (n0 < 2560) { W = Wk; ldw = 512;  wcol0 = n0 - 2048; region = 1; }
    else                { W = Wv; ldw = 512;  wcol0 = n0 - 2560; region = 2; }

    const int tid = threadIdx.x;
    const int tx = tid & 15, ty = tid >> 4;
    const int m0 = bm * 128;

    float acc[8][8];
    #pragma unroll
    for (int i = 0; i < 8; i++)
        #pragma unroll
        for (int j = 0; j < 8; j++) acc[i][j] = 0.f;

    for (int k0 = 0; k0 < CC; k0 += 16) {
        #pragma unroll
        for (int u = 0; u < 2; u++) {
            int l = tid * 2 + u;
            int r = l >> 2, c4 = (l & 3) * 4;
            float4 a = *(const float4*)(x + (size_t)(m0 + r) * CC + k0 + c4);
            As[c4 + 0][r] = a.x; As[c4 + 1][r] = a.y;
            As[c4 + 2][r] = a.z; As[c4 + 3][r] = a.w;
        }
        #pragma unroll
        for (int u = 0; u < 2; u++) {
            int l = tid * 2 + u;
            int r = l >> 5, c4 = (l & 31) * 4;
            *(float4*)(&Bs[r][c4]) =
                *(const float4*)(W + (size_t)(k0 + r) * ldw + wcol0 + c4);
        }
        __syncthreads();
        #pragma unroll
        for (int kk = 0; kk < 16; kk++) {
            float a[8], b[8];
            *(float4*)(a)     = *(float4*)(&As[kk][ty * 8]);
            *(float4*)(a + 4) = *(float4*)(&As[kk][ty * 8 + 4]);
            *(float4*)(b)     = *(float4*)(&Bs[kk][tx * 8]);
            *(float4*)(b + 4) = *(float4*)(&Bs[kk][tx * 8 + 4]);
            #pragma unroll
            for (int i = 0; i < 8; i++)
                #pragma unroll
                for (int j = 0; j < 8; j++) acc[i][j] += a[i] * b[j];
        }
        __syncthreads();
    }

    // store into q/k/v scratch with [B,H,T,HD] layout
    #pragma unroll
    for (int i = 0; i < 8; i++) {
        int m = m0 + ty * 8 + i;
        int b_ = m / TT, t = m % TT;
        #pragma unroll
        for (int j = 0; j < 8; j++) {
            int n = n0 + tx * 8 + j;
            float val = acc[i][j];
            if (region == 0) {
                int hh = n >> 7, d = n & 127;
                g_q[(((size_t)b_ * NH + hh) * TT + t) * HD + d] = val;
            } else {
                int nn = n - (region == 1 ? 2048 : 2560);
                int hh = nn >> 7, d = nn & 127;
                float* dst = (region == 1) ? g_k : g_v;
                dst[(((size_t)b_ * NKV + hh) * TT + t) * HD + d] = val;
            }
        }
    }
}

// ---------------- projection GEMM ------------------------------------------
__global__ __launch_bounds__(256) void proj_gemm(
    const float* __restrict__ Wp, float* __restrict__ out)
{
    __shared__ float As[16][128];
    __shared__ float Bs[16][128];

    const int m0 = blockIdx.x * 128;
    const int n0 = blockIdx.y * 128;
    const int tid = threadIdx.x;
    const int tx = tid & 15, ty = tid >> 4;

    float acc[8][8];
    #pragma unroll
    for (int i = 0; i < 8; i++)
        #pragma unroll
        for (int j = 0; j < 8; j++) acc[i][j] = 0.f;

    for (int k0 = 0; k0 < CC; k0 += 16) {
        #pragma unroll
        for (int u = 0; u < 2; u++) {
            int l = tid * 2 + u;
            int r = l >> 2, c4 = (l & 3) * 4;
            float4 a = *(const float4*)(g_y + (size_t)(m0 + r) * CC + k0 + c4);
            As[c4 + 0][r] = a.x; As[c4 + 1][r] = a.y;
            As[c4 + 2][r] = a.z; As[c4 + 3][r] = a.w;
        }
        #pragma unroll
        for (int u = 0; u < 2; u++) {
            int l = tid * 2 + u;
            int r = l >> 5, c4 = (l & 31) * 4;
            *(float4*)(&Bs[r][c4]) =
                *(const float4*)(Wp + (size_t)(k0 + r) * CC + n0 + c4);
        }
        __syncthreads();
        #pragma unroll
        for (int kk = 0; kk < 16; kk++) {
            float a[8], b[8];
            *(float4*)(a)     = *(float4*)(&As[kk][ty * 8]);
            *(float4*)(a + 4) = *(float4*)(&As[kk][ty * 8 + 4]);
            *(float4*)(b)     = *(float4*)(&Bs[kk][tx * 8]);
            *(float4*)(b + 4) = *(float4*)(&Bs[kk][tx * 8 + 4]);
            #pragma unroll
            for (int i = 0; i < 8; i++)
                #pragma unroll
                for (int j = 0; j < 8; j++) acc[i][j] += a[i] * b[j];
        }
        __syncthreads();
    }
    #pragma unroll
    for (int i = 0; i < 8; i++) {
        size_t m = m0 + ty * 8 + i;
        #pragma unroll
        for (int j = 0; j < 8; j += 4) {
            float4 v = make_float4(acc[i][j], acc[i][j+1], acc[i][j+2], acc[i][j+3]);
            *(float4*)(out + m * CC + n0 + tx * 8 + j) = v;
        }
    }
}

// ---------------- rope + rms (1 warp per 128-wide row) ---------------------
__global__ __launch_bounds__(256) void rope_rms(
    const float* __restrict__ cosp, const float* __restrict__ sinp)
{
    const int nq = BB * NH * TT;
    const int nrows = nq + BB * NKV * TT;
    int w = (blockIdx.x * blockDim.x + threadIdx.x) >> 5;
    if (w >= nrows) return;
    int lane = threadIdx.x & 31;

    float* p;
    int t;
    if (w < nq) { p = g_q + (size_t)w * HD; t = w % TT; }
    else        { int r = w - nq; p = g_k + (size_t)r * HD; t = r % TT; }

    float x0 = p[lane], x1 = p[lane + 32], x2 = p[lane + 64], x3 = p[lane + 96];
    float c0 = cosp[t * 64 + lane],       s0 = sinp[t * 64 + lane];
    float c1 = cosp[t * 64 + lane + 32],  s1 = sinp[t * 64 + lane + 32];

    float o0 =  x0 * c0 + x2 * s0;
    float o2 = -x0 * s0 + x2 * c0;
    float o1 =  x1 * c1 + x3 * s1;
    float o3 = -x1 * s1 + x3 * c1;

    float ss = o0*o0 + o1*o1 + o2*o2 + o3*o3;
    #pragma unroll
    for (int off = 16; off >= 1; off >>= 1)
        ss += __shfl_xor_sync(0xffffffffu, ss, off);
    float scale = rsqrtf(ss * (1.0f / 128.0f) + 1.1920929e-07f);

    p[lane]      = o0 * scale;
    p[lane + 32] = o1 * scale;
    p[lane + 64] = o2 * scale;
    p[lane + 96] = o3 * scale;
}

// ---------------- v += 2*sigmoid(x[:,:32]@Wgate) * ve ----------------------
__global__ __launch_bounds__(512) void vgate(
    const float* __restrict__ x, const float* __restrict__ ve,
    const float* __restrict__ Wg)
{
    __shared__ float xs[GC];
    __shared__ float gs[NKV];
    const int bt = blockIdx.x;
    const int b_ = bt / TT, t = bt % TT;
    const int tid = threadIdx.x;

    if (tid < GC) xs[tid] = x[(size_t)bt * CC + tid];
    __syncthreads();
    if (tid < NKV) {
        float s = 0.f;
        #pragma unroll
        for (int g = 0; g < GC; g++) s += xs[g] * Wg[g * NKV + tid];
        gs[tid] = 2.0f / (1.0f + expf(-s));
    }
    __syncthreads();
    int kv = tid >> 7, d = tid & 127;
    size_t vi = (((size_t)b_ * NKV + kv) * TT + t) * HD + d;
    g_v[vi] += gs[kv] * ve[(size_t)bt * (NKV * HD) + kv * HD + d];
}

// ---------------- flash attention ------------------------------------------
#define BQ 64
#define BKV 64
#define QPAD (HD + 1)
#define PPAD (BKV + 1)
#define ATTN_SMEM ((3 * BQ * QPAD + BQ * PPAD + 3 * BQ) * 4)

__global__ __launch_bounds__(256) void attn_kernel()
{
    extern __shared__ float sm[];
    float* Qs  = sm;                         // [BQ][QPAD]
    float* Ks  = Qs + BQ * QPAD;             // [BKV][QPAD]
    float* Vs  = Ks + BKV * QPAD;            // [BKV][QPAD]
    float* Ps  = Vs + BKV * QPAD;            // [BQ][PPAD]
    float* m_s = Ps + BQ * PPAD;
    float* l_s = m_s + BQ;
    float* al_s = l_s + BQ;

    const int tid = threadIdx.x;
    const int tx = tid & 15, ty = tid >> 4;
    const int q0 = blockIdx.x * BQ;
    const int bh = blockIdx.y;
    const int b_ = bh / NH, h = bh % NH;
    const int kvh = h >> 2;

    const float* qbase = g_q + ((size_t)b_ * NH + h)   * TT * HD;
    const float* kbase = g_k + ((size_t)b_ * NKV + kvh) * TT * HD;
    const float* vbase = g_v + ((size_t)b_ * NKV + kvh) * TT * HD;
    const float qscale = 0.08838834764831845f;   // 1/sqrt(128)

    // load Q tile (scaled)
    for (int i = tid; i < BQ * HD / 4; i += 256) {
        int r = i >> 5, c4 = (i & 31) * 4;
        float4 v = *(const float4*)(qbase + (size_t)(q0 + r) * HD + c4);
        Qs[r * QPAD + c4 + 0] = v.x * qscale;
        Qs[r * QPAD + c4 + 1] = v.y * qscale;
        Qs[r * QPAD + c4 + 2] = v.z * qscale;
        Qs[r * QPAD + c4 + 3] = v.w * qscale;
    }
    if (tid < BQ) { m_s[tid] = -1e30f; l_s[tid] = 0.f; }

    float o[4][8];
    #pragma unroll
    for (int i = 0; i < 4; i++)
        #pragma unroll
        for (int j = 0; j < 8; j++) o[i][j] = 0.f;
    __syncthreads();

    const int ntiles = blockIdx.x + 1;
    for (int kt = 0; kt < ntiles; kt++) {
        const int k0 = kt * BKV;
        for (int i = tid; i < BKV * HD / 4; i += 256) {
            int r = i >> 5, c4 = (i & 31) * 4;
            float4 kv4 = *(const float4*)(kbase + (size_t)(k0 + r) * HD + c4);
            Ks[r * QPAD + c4 + 0] = kv4.x; Ks[r * QPAD + c4 + 1] = kv4.y;
            Ks[r * QPAD + c4 + 2] = kv4.z; Ks[r * QPAD + c4 + 3] = kv4.w;
            float4 vv4 = *(const float4*)(vbase + (size_t)(k0 + r) * HD + c4);
            Vs[r * QPAD + c4 + 0] = vv4.x; Vs[r * QPAD + c4 + 1] = vv4.y;
            Vs[r * QPAD + c4 + 2] = vv4.z; Vs[r * QPAD + c4 + 3] = vv4.w;
        }
        __syncthreads();

        // S = Q K^T : thread rows {ty+16i}, cols {tx+16j}
        float s[4][4];
        #pragma unroll
        for (int i = 0; i < 4; i++)
            #pragma unroll
            for (int j = 0; j < 4; j++) s[i][j] = 0.f;

        for (int d = 0; d < HD; d++) {
            float qv[4], kv[4];
            #pragma unroll
            for (int i = 0; i < 4; i++) qv[i] = Qs[(ty + 16 * i) * QPAD + d];
            #pragma unroll
            for (int j = 0; j < 4; j++) kv[j] = Ks[(tx + 16 * j) * QPAD + d];
            #pragma unroll
            for (int i = 0; i < 4; i++)
                #pragma unroll
                for (int j = 0; j < 4; j++) s[i][j] += qv[i] * kv[j];
        }

        if (k0 + BKV > q0) {  // diagonal tile: causal mask
            #pragma unroll
            for (int i = 0; i < 4; i++)
                #pragma unroll
                for (int j = 0; j < 4; j++)
                    if (k0 + tx + 16 * j > q0 + ty + 16 * i) s[i][j] = -1e30f;
        }

        // online softmax (rows owned by 16 lanes sharing ty)
        float mnew[4], alpha[4], rowsum[4];
        #pragma unroll
        for (int i = 0; i < 4; i++) {
            int r = ty + 16 * i;
            float mx = fmaxf(fmaxf(s[i][0], s[i][1]), fmaxf(s[i][2], s[i][3]));
            #pragma unroll
            for (int off = 8; off >= 1; off >>= 1)
                mx = fmaxf(mx, __shfl_xor_sync(0xffffffffu, mx, off));
            float mold = m_s[r];
            mnew[i] = fmaxf(mold, mx);
            alpha[i] = expf(mold - mnew[i]);
            float rs = 0.f;
            #pragma unroll
            for (int j = 0; j < 4; j++) {
                float pv = expf(s[i][j] - mnew[i]);
                Ps[r * PPAD + tx + 16 * j] = pv;
                rs += pv;
            }
            #pragma unroll
            for (int off = 8; off >= 1; off >>= 1)
                rs += __shfl_xor_sync(0xffffffffu, rs, off);
            rowsum[i] = rs;
        }
        __syncwarp(0xffffffffu);
        if (tx == 0) {
            #pragma unroll
            for (int i = 0; i < 4; i++) {
                int r = ty + 16 * i;
                m_s[r] = mnew[i];
                al_s[r] = alpha[i];
                l_s[r] = l_s[r] * alpha[i] + rowsum[i];
            }
        }
        __syncthreads();

        // O = O*alpha + P V : rows {ty+16i}, cols {tx+16j}
        float a_[4];
        #pragma unroll
        for (int i = 0; i < 4; i++) a_[i] = al_s[ty + 16 * i];
        #pragma unroll
        for (int i = 0; i < 4; i++)
            #pragma unroll
            for (int j = 0; j < 8; j++) o[i][j] *= a_[i];

        for (int jj = 0; jj < BKV; jj++) {
            float p4[4], v8[8];
            #pragma unroll
            for (int i = 0; i < 4; i++) p4[i] = Ps[(ty + 16 * i) * PPAD + jj];
            #pragma unroll
            for (int j = 0; j < 8; j++) v8[j] = Vs[jj * QPAD + tx + 16 * j];
            #pragma unroll
            for (int i = 0; i < 4; i++)
                #pragma unroll
                for (int j = 0; j < 8; j++) o[i][j] += p4[i] * v8[j];
        }
        __syncthreads();
    }

    // epilogue: write y in [B,T,NH,HD] layout
    #pragma unroll
    for (int i = 0; i < 4; i++) {
        int r = ty + 16 * i;
        float inv = 1.0f / l_s[r];
        size_t base = ((size_t)(b_ * TT + q0 + r) * NH + h) * HD;
        #pragma unroll
        for (int j = 0; j < 8; j++)
            g_y[base + tx + 16 * j] = o[i][j] * inv;
    }
}

// ---------------- launch ----------------------------------------------------
extern "C" void kernel_launch(void* const* d_in, const int* in_sizes, int n_in,
                              void* d_out, int out_size)
{
    const float* x     = (const float*)d_in[0];
    const float* ve    = (const float*)d_in[1];
    const float* cosp  = (const float*)d_in[2];
    const float* sinp  = (const float*)d_in[3];
    const float* Wq    = (const float*)d_in[4];
    const float* Wk    = (const float*)d_in[5];
    const float* Wv    = (const float*)d_in[6];
    const float* Wproj = (const float*)d_in[7];
    const float* Wgate = (const float*)d_in[8];
    float* out = (float*)d_out;

    dim3 g1(BT / 128, 3072 / 128);
    qkv_gemm<<<g1, 256>>>(x, Wq, Wk, Wv);

    int nrows = BB * NH * TT + BB * NKV * TT;     // 81920 rows, 1 warp each
    int blocks = (nrows * 32 + 255) / 256;
    rope_rms<<<blocks, 256>>>(cosp, sinp);

    vgate<<<BT, 512>>>(x, ve, Wgate);

    cudaFuncSetAttribute(attn_kernel,
                         cudaFuncAttributeMaxDynamicSharedMemorySize, ATTN_SMEM);
    attn_kernel<<<dim3(TT / BQ, BB * NH), 256, ATTN_SMEM>>>();

    dim3 g2(BT / 128, CC / 128);
    proj_gemm<<<g2, 256>>>(Wproj, out);
}

// round 2
// speedup vs baseline: 3.8271x; 3.8271x over previous
#include <cuda_runtime.h>
#include <math.h>
#include <stdint.h>

#define BB 2
#define TT 2048
#define CC 2048
#define NH 16
#define NKV 4
#define HD 128
#define GC 32
#define BT (BB*TT)
#define NQKV 3072

// ---------------- scratch (device globals; no allocation allowed) -----------
__device__ float g_x[(size_t)BT*CC];        // tf32-rounded x
__device__ float g_wqkv[(size_t)CC*NQKV];   // tf32-rounded [Wq|Wk|Wv]
__device__ float g_wproj[(size_t)CC*CC];    // tf32-rounded Wproj
__device__ float g_q[(size_t)BB*NH*TT*HD];  // [B,NH,T,HD]
__device__ float g_k[(size_t)BB*NKV*TT*HD]; // [B,NKV,T,HD]
__device__ float g_v[(size_t)BB*NKV*TT*HD]; // [B,NKV,T,HD]
__device__ float g_y[(size_t)BT*CC];        // [B,T,NH,HD] == [BT,C], tf32-rounded

// ---------------- helpers ---------------------------------------------------
__device__ __forceinline__ float tf32r(float x){
    uint32_t u;
    asm("cvt.rna.tf32.f32 %0, %1;" : "=r"(u) : "f"(x));
    return __uint_as_float(u);
}
__device__ __forceinline__ void mma_tf32(float* c,
    uint32_t a0, uint32_t a1, uint32_t a2, uint32_t a3,
    uint32_t b0, uint32_t b1)
{
    asm volatile("mma.sync.aligned.m16n8k8.row.col.f32.tf32.tf32.f32 "
        "{%0,%1,%2,%3}, {%4,%5,%6,%7}, {%8,%9}, {%0,%1,%2,%3};"
        : "+f"(c[0]), "+f"(c[1]), "+f"(c[2]), "+f"(c[3])
        : "r"(a0), "r"(a1), "r"(a2), "r"(a3), "r"(b0), "r"(b1));
}
__device__ __forceinline__ void cpa16(float* s, const float* g){
    uint32_t sa = (uint32_t)__cvta_generic_to_shared(s);
    asm volatile("cp.async.cg.shared.global [%0], [%1], 16;" :: "r"(sa), "l"(g));
}
#define CPA_COMMIT() asm volatile("cp.async.commit_group;")
#define CPA_WAIT0()  asm volatile("cp.async.wait_group 0;")

__device__ __forceinline__ float4 tf32r4(float4 v){
    v.x = tf32r(v.x); v.y = tf32r(v.y); v.z = tf32r(v.z); v.w = tf32r(v.w);
    return v;
}

// ---------------- tf32 pre-rounding kernels ---------------------------------
__global__ __launch_bounds__(256) void cvt_x_kernel(const float* __restrict__ x){
    size_t i = ((size_t)blockIdx.x * 256 + threadIdx.x) * 4;
    *(float4*)(g_x + i) = tf32r4(*(const float4*)(x + i));
}
__global__ __launch_bounds__(256) void cvt_proj_kernel(const float* __restrict__ Wp){
    size_t i = ((size_t)blockIdx.x * 256 + threadIdx.x) * 4;
    *(float4*)(g_wproj + i) = tf32r4(*(const float4*)(Wp + i));
}
__global__ __launch_bounds__(256) void cvt_wqkv_kernel(
    const float* __restrict__ Wq, const float* __restrict__ Wk,
    const float* __restrict__ Wv)
{
    int k = blockIdx.x;   // 0..2047
    for (int c4 = threadIdx.x * 4; c4 < NQKV; c4 += 256 * 4) {
        const float* src;
        if (c4 < 2048)      src = Wq + (size_t)k * 2048 + c4;
        else if (c4 < 2560) src = Wk + (size_t)k * 512 + (c4 - 2048);
        else                src = Wv + (size_t)k * 512 + (c4 - 2560);
        *(float4*)(g_wqkv + (size_t)k * NQKV + c4) = tf32r4(*(const float4*)src);
    }
}

// ---------------- tf32 GEMM: C[4096,3072] = g_x @ g_wqkv --------------------
#define GLDA 36
#define GLDB 136
#define GEMM_SMEM ((2*128*GLDA + 2*32*GLDB) * 4)

__global__ __launch_bounds__(256) void qkv_gemm()
{
    extern __shared__ float sm[];
    float* As  = sm;                 // [2][128][36]
    float* Bsm = sm + 2*128*GLDA;    // [2][32][136]
    const int tid = threadIdx.x, lane = tid & 31, warp = tid >> 5;
    const int wm = warp & 1, wn = warp >> 1;
    const int m0 = blockIdx.x * 128, n0 = blockIdx.y * 128;

    float acc[4][4][4];
    #pragma unroll
    for (int a = 0; a < 4; a++)
        #pragma unroll
        for (int b = 0; b < 4; b++)
            #pragma unroll
            for (int c = 0; c < 4; c++) acc[a][b][c] = 0.f;

    // prefetch chunk 0
    #pragma unroll
    for (int i = 0; i < 4; i++) {
        int idx = tid + i * 256;
        int r = idx >> 3, c4 = (idx & 7) * 4;
        cpa16(&As[r*GLDA + c4], &g_x[(size_t)(m0 + r) * CC + c4]);
    }
    #pragma unroll
    for (int i = 0; i < 4; i++) {
        int idx = tid + i * 256;
        int r = idx >> 5, c4 = (idx & 31) * 4;
        cpa16(&Bsm[r*GLDB + c4], &g_wqkv[(size_t)r * NQKV + n0 + c4]);
    }
    CPA_COMMIT();

    for (int ch = 0; ch < 64; ch++) {
        CPA_WAIT0();
        __syncthreads();
        if (ch + 1 < 64) {
            int k0 = (ch + 1) * 32, buf = (ch + 1) & 1;
            #pragma unroll
            for (int i = 0; i < 4; i++) {
                int idx = tid + i * 256;
                int r = idx >> 3, c4 = (idx & 7) * 4;
                cpa16(&As[buf*128*GLDA + r*GLDA + c4],
                      &g_x[(size_t)(m0 + r) * CC + k0 + c4]);
            }
            #pragma unroll
            for (int i = 0; i < 4; i++) {
                int idx = tid + i * 256;
                int r = idx >> 5, c4 = (idx & 31) * 4;
                cpa16(&Bsm[buf*32*GLDB + r*GLDB + c4],
                      &g_wqkv[(size_t)(k0 + r) * NQKV + n0 + c4]);
            }
            CPA_COMMIT();
        }
        const float* Ab = &As[(ch & 1)*128*GLDA + (wm*64)*GLDA];
        const float* Bb = &Bsm[(ch & 1)*32*GLDB];
        #pragma unroll
        for (int kk = 0; kk < 4; kk++) {
            uint32_t a[4][4], b[4][2];
            #pragma unroll
            for (int mt = 0; mt < 4; mt++) {
                const float* p = Ab + (mt*16 + (lane>>2))*GLDA + kk*8 + (lane&3);
                a[mt][0] = __float_as_uint(p[0]);
                a[mt][1] = __float_as_uint(p[8*GLDA]);
                a[mt][2] = __float_as_uint(p[4]);
                a[mt][3] = __float_as_uint(p[8*GLDA + 4]);
            }
            #pragma unroll
            for (int nt = 0; nt < 4; nt++) {
                const float* p = Bb + (kk*8 + (lane&3))*GLDB + wn*32 + nt*8 + (lane>>2);
                b[nt][0] = __float_as_uint(p[0]);
                b[nt][1] = __float_as_uint(p[4*GLDB]);
            }
            #pragma unroll
            for (int mt = 0; mt < 4; mt++)
                #pragma unroll
                for (int nt = 0; nt < 4; nt++)
                    mma_tf32(acc[mt][nt], a[mt][0], a[mt][1], a[mt][2], a[mt][3],
                             b[nt][0], b[nt][1]);
        }
    }

    // epilogue: scatter to q/k/v ([B,H,T,HD] layouts)
    #pragma unroll
    for (int mt = 0; mt < 4; mt++) {
        #pragma unroll
        for (int rr = 0; rr < 2; rr++) {
            int m = m0 + wm*64 + mt*16 + (lane>>2) + rr*8;
            int b_ = m / TT, t = m % TT;
            #pragma unroll
            for (int nt = 0; nt < 4; nt++) {
                int n = n0 + wn*32 + nt*8 + 2*(lane&3);
                float2 v;
                v.x = acc[mt][nt][rr*2 + 0];
                v.y = acc[mt][nt][rr*2 + 1];
                float* dst;
                if (n < 2048) {
                    int hh = n >> 7, d = n & 127;
                    dst = &g_q[(((size_t)b_*NH + hh)*TT + t)*HD + d];
                } else if (n < 2560) {
                    int nn = n - 2048; int hh = nn >> 7, d = nn & 127;
                    dst = &g_k[(((size_t)b_*NKV + hh)*TT + t)*HD + d];
                } else {
                    int nn = n - 2560; int hh = nn >> 7, d = nn & 127;
                    dst = &g_v[(((size_t)b_*NKV + hh)*TT + t)*HD + d];
                }
                *(float2*)dst = v;
            }
        }
    }
}

// ---------------- tf32 GEMM: out[4096,2048] = g_y @ g_wproj -----------------
__global__ __launch_bounds__(256) void proj_gemm(float* __restrict__ out)
{
    extern __shared__ float sm[];
    float* As  = sm;
    float* Bsm = sm + 2*128*GLDA;
    const int tid = threadIdx.x, lane = tid & 31, warp = tid >> 5;
    const int wm = warp & 1, wn = warp >> 1;
    const int m0 = blockIdx.x * 128, n0 = blockIdx.y * 128;

    float acc[4][4][4];
    #pragma unroll
    for (int a = 0; a < 4; a++)
        #pragma unroll
        for (int b = 0; b < 4; b++)
            #pragma unroll
            for (int c = 0; c < 4; c++) acc[a][b][c] = 0.f;

    #pragma unroll
    for (int i = 0; i < 4; i++) {
        int idx = tid + i * 256;
        int r = idx >> 3, c4 = (idx & 7) * 4;
        cpa16(&As[r*GLDA + c4], &g_y[(size_t)(m0 + r) * CC + c4]);
    }
    #pragma unroll
    for (int i = 0; i < 4; i++) {
        int idx = tid + i * 256;
        int r = idx >> 5, c4 = (idx & 31) * 4;
        cpa16(&Bsm[r*GLDB + c4], &g_wproj[(size_t)r * CC + n0 + c4]);
    }
    CPA_COMMIT();

    for (int ch = 0; ch < 64; ch++) {
        CPA_WAIT0();
        __syncthreads();
        if (ch + 1 < 64) {
            int k0 = (ch + 1) * 32, buf = (ch + 1) & 1;
            #pragma unroll
            for (int i = 0; i < 4; i++) {
                int idx = tid + i * 256;
                int r = idx >> 3, c4 = (idx & 7) * 4;
                cpa16(&As[buf*128*GLDA + r*GLDA + c4],
                      &g_y[(size_t)(m0 + r) * CC + k0 + c4]);
            }
            #pragma unroll
            for (int i = 0; i < 4; i++) {
                int idx = tid + i * 256;
                int r = idx >> 5, c4 = (idx & 31) * 4;
                cpa16(&Bsm[buf*32*GLDB + r*GLDB + c4],
                      &g_wproj[(size_t)(k0 + r) * CC + n0 + c4]);
            }
            CPA_COMMIT();
        }
        const float* Ab = &As[(ch & 1)*128*GLDA + (wm*64)*GLDA];
        const float* Bb = &Bsm[(ch & 1)*32*GLDB];
        #pragma unroll
        for (int kk = 0; kk < 4; kk++) {
            uint32_t a[4][4], b[4][2];
            #pragma unroll
            for (int mt = 0; mt < 4; mt++) {
                const float* p = Ab + (mt*16 + (lane>>2))*GLDA + kk*8 + (lane&3);
                a[mt][0] = __float_as_uint(p[0]);
                a[mt][1] = __float_as_uint(p[8*GLDA]);
                a[mt][2] = __float_as_uint(p[4]);
                a[mt][3] = __float_as_uint(p[8*GLDA + 4]);
            }
            #pragma unroll
            for (int nt = 0; nt < 4; nt++) {
                const float* p = Bb + (kk*8 + (lane&3))*GLDB + wn*32 + nt*8 + (lane>>2);
                b[nt][0] = __float_as_uint(p[0]);
                b[nt][1] = __float_as_uint(p[4*GLDB]);
            }
            #pragma unroll
            for (int mt = 0; mt < 4; mt++)
                #pragma unroll
                for (int nt = 0; nt < 4; nt++)
                    mma_tf32(acc[mt][nt], a[mt][0], a[mt][1], a[mt][2], a[mt][3],
                             b[nt][0], b[nt][1]);
        }
    }

    #pragma unroll
    for (int mt = 0; mt < 4; mt++) {
        #pragma unroll
        for (int rr = 0; rr < 2; rr++) {
            size_t m = m0 + wm*64 + mt*16 + (lane>>2) + rr*8;
            #pragma unroll
            for (int nt = 0; nt < 4; nt++) {
                int n = n0 + wn*32 + nt*8 + 2*(lane&3);
                float2 v;
                v.x = acc[mt][nt][rr*2 + 0];
                v.y = acc[mt][nt][rr*2 + 1];
                *(float2*)(out + m * CC + n) = v;
            }
        }
    }
}

// ---------------- rope + rms (+ tf32 round; q pre-scaled by 1/sqrt(HD)) ----
__global__ __launch_bounds__(256) void rope_rms(
    const float* __restrict__ cosp, const float* __restrict__ sinp)
{
    const int nq = BB * NH * TT;
    const int nrows = nq + BB * NKV * TT;
    int w = (blockIdx.x * blockDim.x + threadIdx.x) >> 5;
    if (w >= nrows) return;
    int lane = threadIdx.x & 31;

    float* p;
    int t;
    float qs;
    if (w < nq) { p = g_q + (size_t)w * HD; t = w % TT; qs = 0.08838834764831845f; }
    else        { int r = w - nq; p = g_k + (size_t)r * HD; t = r % TT; qs = 1.0f; }

    float x0 = p[lane], x1 = p[lane + 32], x2 = p[lane + 64], x3 = p[lane + 96];
    float c0 = cosp[t * 64 + lane],      s0 = sinp[t * 64 + lane];
    float c1 = cosp[t * 64 + lane + 32], s1 = sinp[t * 64 + lane + 32];

    float o0 =  x0 * c0 + x2 * s0;
    float o2 = -x0 * s0 + x2 * c0;
    float o1 =  x1 * c1 + x3 * s1;
    float o3 = -x1 * s1 + x3 * c1;

    float ss = o0*o0 + o1*o1 + o2*o2 + o3*o3;
    #pragma unroll
    for (int off = 16; off >= 1; off >>= 1)
        ss += __shfl_xor_sync(0xffffffffu, ss, off);
    float scale = rsqrtf(ss * (1.0f / 128.0f) + 1.1920929e-07f) * qs;

    p[lane]      = tf32r(o0 * scale);
    p[lane + 32] = tf32r(o1 * scale);
    p[lane + 64] = tf32r(o2 * scale);
    p[lane + 96] = tf32r(o3 * scale);
}

// ---------------- v = tf32(v + 2*sigmoid(x[:,:32]@Wgate) * ve) --------------
__global__ __launch_bounds__(512) void vgate(
    const float* __restrict__ x, const float* __restrict__ ve,
    const float* __restrict__ Wg)
{
    __shared__ float xs[GC];
    __shared__ float gs[NKV];
    const int bt = blockIdx.x;
    const int b_ = bt / TT, t = bt % TT;
    const int tid = threadIdx.x;

    if (tid < GC) xs[tid] = x[(size_t)bt * CC + tid];
    __syncthreads();
    if (tid < NKV) {
        float s = 0.f;
        #pragma unroll
        for (int g = 0; g < GC; g++) s += xs[g] * Wg[g * NKV + tid];
        gs[tid] = 2.0f / (1.0f + expf(-s));
    }
    __syncthreads();
    int kv = tid >> 7, d = tid & 127;
    size_t vi = (((size_t)b_ * NKV + kv) * TT + t) * HD + d;
    g_v[vi] = tf32r(g_v[vi] + gs[kv] * ve[(size_t)bt * (NKV * HD) + kv * HD + d]);
}

// ---------------- flash attention (tf32 mma) --------------------------------
// BQ=128, BKV=64, 256 threads (8 warps)
#define AQ_LD 132
#define AK_LD 132
#define AV_LD 136
#define AP_LD 68
#define OFF_K (128*AQ_LD)
#define OFF_V (OFF_K + 64*AK_LD)
#define OFF_P (OFF_V + 64*AV_LD)
#define OFF_M (OFF_P + 128*AP_LD)
#define OFF_L (OFF_M + 128)
#define OFF_AL (OFF_L + 128)
#define ATTN_SMEM ((OFF_AL + 128) * 4)

__global__ __launch_bounds__(256) void attn_kernel()
{
    extern __shared__ float sm[];
    float* Qs  = sm;
    float* Ks  = sm + OFF_K;
    float* Vs  = sm + OFF_V;
    float* Ps  = sm + OFF_P;
    float* m_s = sm + OFF_M;
    float* l_s = sm + OFF_L;
    float* al_s = sm + OFF_AL;

    const int tid = threadIdx.x, lane = tid & 31, warp = tid >> 5;
    const int wm = warp >> 1, wn = warp & 1;
    const int q0 = blockIdx.x * 128;
    const int bh = blockIdx.y;
    const int b_ = bh / NH, h = bh % NH;
    const int kvh = h >> 2;

    const float* qbase = g_q + ((size_t)b_ * NH + h) * TT * HD + (size_t)q0 * HD;
    const float* kbase = g_k + ((size_t)b_ * NKV + kvh) * TT * HD;
    const float* vbase = g_v + ((size_t)b_ * NKV + kvh) * TT * HD;

    // load Q tile (already tf32-rounded and pre-scaled by 1/sqrt(HD))
    #pragma unroll
    for (int i = 0; i < 16; i++) {
        int idx = tid + i * 256;
        int r = idx >> 5, c4 = (idx & 31) * 4;
        *(float4*)(&Qs[r * AQ_LD + c4]) = *(const float4*)(qbase + (size_t)r * HD + c4);
    }
    if (tid < 128) { m_s[tid] = -1e30f; l_s[tid] = 0.f; }

    float o[2][8][4];
    #pragma unroll
    for (int mt = 0; mt < 2; mt++)
        #pragma unroll
        for (int nt = 0; nt < 8; nt++)
            #pragma unroll
            for (int c = 0; c < 4; c++) o[mt][nt][c] = 0.f;
    __syncthreads();

    const int ntiles = 2 * blockIdx.x + 2;
    for (int kt = 0; kt < ntiles; kt++) {
        const int k0 = kt * 64;
        // load K, V tiles
        #pragma unroll
        for (int i = 0; i < 8; i++) {
            int idx = tid + i * 256;
            int r = idx >> 5, c4 = (idx & 31) * 4;
            *(float4*)(&Ks[r * AK_LD + c4]) = *(const float4*)(kbase + (size_t)(k0 + r) * HD + c4);
            *(float4*)(&Vs[r * AV_LD + c4]) = *(const float4*)(vbase + (size_t)(k0 + r) * HD + c4);
        }
        __syncthreads();

        // S = Q K^T  (warp tile 32x32: wm rows, wn cols)
        float s[2][4][4];
        #pragma unroll
        for (int mt = 0; mt < 2; mt++)
            #pragma unroll
            for (int nt = 0; nt < 4; nt++)
                #pragma unroll
                for (int c = 0; c < 4; c++) s[mt][nt][c] = 0.f;

        #pragma unroll
        for (int kk = 0; kk < 16; kk++) {
            uint32_t a[2][4], b[4][2];
            #pragma unroll
            for (int mt = 0; mt < 2; mt++) {
                const float* p = &Qs[(wm*32 + mt*16 + (lane>>2)) * AQ_LD + kk*8 + (lane&3)];
                a[mt][0] = __float_as_uint(p[0]);
                a[mt][1] = __float_as_uint(p[8*AQ_LD]);
                a[mt][2] = __float_as_uint(p[4]);
                a[mt][3] = __float_as_uint(p[8*AQ_LD + 4]);
            }
            #pragma unroll
            for (int nt = 0; nt < 4; nt++) {
                const float* p = &Ks[(wn*32 + nt*8 + (lane>>2)) * AK_LD + kk*8 + (lane&3)];
                b[nt][0] = __float_as_uint(p[0]);
                b[nt][1] = __float_as_uint(p[4]);
            }
            #pragma unroll
            for (int mt = 0; mt < 2; mt++)
                #pragma unroll
                for (int nt = 0; nt < 4; nt++)
                    mma_tf32(s[mt][nt], a[mt][0], a[mt][1], a[mt][2], a[mt][3],
                             b[nt][0], b[nt][1]);
        }

        // store S -> Ps
        #pragma unroll
        for (int mt = 0; mt < 2; mt++) {
            int r = wm*32 + mt*16 + (lane>>2);
            #pragma unroll
            for (int nt = 0; nt < 4; nt++) {
                int cc = wn*32 + nt*8 + 2*(lane&3);
                float2 v0; v0.x = s[mt][nt][0]; v0.y = s[mt][nt][1];
                float2 v1; v1.x = s[mt][nt][2]; v1.y = s[mt][nt][3];
                *(float2*)(&Ps[r * AP_LD + cc])       = v0;
                *(float2*)(&Ps[(r + 8) * AP_LD + cc]) = v1;
            }
        }
        __syncthreads();

        // online softmax: 2 threads per row
        {
            int r = tid >> 1, hh = tid & 1;
            bool dia = (kt >= ntiles - 2);
            float vals[32];
            #pragma unroll
            for (int j = 0; j < 8; j++) {
                float4 v4 = *(float4*)(&Ps[r * AP_LD + hh*32 + j*4]);
                vals[j*4 + 0] = v4.x; vals[j*4 + 1] = v4.y;
                vals[j*4 + 2] = v4.z; vals[j*4 + 3] = v4.w;
            }
            if (dia) {
                #pragma unroll
                for (int c = 0; c < 32; c++)
                    if (k0 + hh*32 + c > q0 + r) vals[c] = -1e30f;
            }
            float mx = -1e30f;
            #pragma unroll
            for (int c = 0; c < 32; c++) mx = fmaxf(mx, vals[c]);
            mx = fmaxf(mx, __shfl_xor_sync(0xffffffffu, mx, 1));
            float mold = m_s[r];
            float mnew = fmaxf(mold, mx);
            float alpha = __expf(mold - mnew);
            float rs = 0.f;
            #pragma unroll
            for (int c = 0; c < 32; c++) {
                float pv = __expf(vals[c] - mnew);
                rs += pv;
                Ps[r * AP_LD + hh*32 + c] = tf32r(pv);
            }
            rs += __shfl_xor_sync(0xffffffffu, rs, 1);
            if (hh == 0) {
                m_s[r]  = mnew;
                al_s[r] = alpha;
                l_s[r]  = l_s[r] * alpha + rs;
            }
        }
        __syncthreads();

        // O = O*alpha + P V  (warp tile 32x64: wm rows, wn cols)
        #pragma unroll
        for (int mt = 0; mt < 2; mt++) {
            int r = wm*32 + mt*16 + (lane>>2);
            float aL = al_s[r], aH = al_s[r + 8];
            #pragma unroll
            for (int nt = 0; nt < 8; nt++) {
                o[mt][nt][0] *= aL; o[mt][nt][1] *= aL;
                o[mt][nt][2] *= aH; o[mt][nt][3] *= aH;
            }
        }
        #pragma unroll
        for (int kk = 0; kk < 8; kk++) {
            uint32_t a[2][4], b[8][2];
            #pragma unroll
            for (int mt = 0; mt < 2; mt++) {
                const float* p = &Ps[(wm*32 + mt*16 + (lane>>2)) * AP_LD + kk*8 + (lane&3)];
                a[mt][0] = __float_as_uint(p[0]);
                a[mt][1] = __float_as_uint(p[8*AP_LD]);
                a[mt][2] = __float_as_uint(p[4]);
                a[mt][3] = __float_as_uint(p[8*AP_LD + 4]);
            }
            #pragma unroll
            for (int nt = 0; nt < 8; nt++) {
                const float* p = &Vs[(kk*8 + (lane&3)) * AV_LD + wn*64 + nt*8 + (lane>>2)];
                b[nt][0] = __float_as_uint(p[0]);
                b[nt][1] = __float_as_uint(p[4*AV_LD]);
            }
            #pragma unroll
            for (int mt = 0; mt < 2; mt++)
                #pragma unroll
                for (int nt = 0; nt < 8; nt++)
                    mma_tf32(o[mt][nt], a[mt][0], a[mt][1], a[mt][2], a[mt][3],
                             b[nt][0], b[nt][1]);
        }
        __syncthreads();
    }

    // epilogue: O / l, tf32-round, write g_y [BT][C]
    #pragma unroll
    for (int mt = 0; mt < 2; mt++) {
        #pragma unroll
        for (int rr = 0; rr < 2; rr++) {
            int r = wm*32 + mt*16 + (lane>>2) + rr*8;
            float inv = 1.0f / l_s[r];
            size_t base = (size_t)(b_ * TT + q0 + r) * CC + h * HD;
            #pragma unroll
            for (int nt = 0; nt < 8; nt++) {
                int d = wn*64 + nt*8 + 2*(lane&3);
                float2 v;
                v.x = tf32r(o[mt][nt][rr*2 + 0] * inv);
                v.y = tf32r(o[mt][nt][rr*2 + 1] * inv);
                *(float2*)(&g_y[base + d]) = v;
            }
        }
    }
}

// ---------------- launch ----------------------------------------------------
extern "C" void kernel_launch(void* const* d_in, const int* in_sizes, int n_in,
                              void* d_out, int out_size)
{
    const float* x     = (const float*)d_in[0];
    const float* ve    = (const float*)d_in[1];
    const float* cosp  = (const float*)d_in[2];
    const float* sinp  = (const float*)d_in[3];
    const float* Wq    = (const float*)d_in[4];
    const float* Wk    = (const float*)d_in[5];
    const float* Wv    = (const float*)d_in[6];
    const float* Wproj = (const float*)d_in[7];
    const float* Wgate = (const float*)d_in[8];
    float* out = (float*)d_out;

    static bool attr_done = false;
    if (!attr_done) {
        cudaFuncSetAttribute(qkv_gemm, cudaFuncAttributeMaxDynamicSharedMemorySize, GEMM_SMEM);
        cudaFuncSetAttribute(proj_gemm, cudaFuncAttributeMaxDynamicSharedMemorySize, GEMM_SMEM);
        cudaFuncSetAttribute(attn_kernel, cudaFuncAttributeMaxDynamicSharedMemorySize, ATTN_SMEM);
        attr_done = true;
    }

    cvt_x_kernel<<<(int)((size_t)BT*CC/4/256), 256>>>(x);
    cvt_wqkv_kernel<<<CC, 256>>>(Wq, Wk, Wv);
    cvt_proj_kernel<<<(int)((size_t)CC*CC/4/256), 256>>>(Wproj);

    qkv_gemm<<<dim3(BT/128, NQKV/128), 256, GEMM_SMEM>>>();

    int nrows = BB * NH * TT + BB * NKV * TT;
    rope_rms<<<(nrows * 32 + 255) / 256, 256>>>(cosp, sinp);

    vgate<<<BT, 512>>>(x, ve, Wgate);

    attn_kernel<<<dim3(TT/128, BB*NH), 256, ATTN_SMEM>>>();

    proj_gemm<<<dim3(BT/128, CC/128), 256, GEMM_SMEM>>>(out);
}